// round 9
// baseline (speedup 1.0000x reference)
#include <cuda_runtime.h>
#include <cstdint>

#define N_IMG 128
#define N_REG 36
#define N_CAP 128
#define N_WORD 32
#define DIM 1024

// Scratch (device globals — no runtime allocation)
__device__ float g_raw[N_CAP * N_IMG * N_REG * N_WORD];   // 75.5 MB
__device__ float g_G[N_IMG * N_REG * N_REG];
__device__ float g_H[N_CAP * N_WORD * N_WORD];

typedef unsigned long long u64;

__device__ __forceinline__ u64 ffma2(u64 a, u64 b, u64 c) {
    u64 d;
    asm("fma.rn.f32x2 %0, %1, %2, %3;" : "=l"(d) : "l"(a), "l"(b), "l"(c));
    return d;
}
__device__ __forceinline__ u64 pack_dup(float x) {
    u64 d;
    asm("mov.b64 %0, {%1, %1};" : "=l"(d) : "f"(x));
    return d;
}
__device__ __forceinline__ void unpack2(u64 v, float& lo, float& hi) {
    asm("mov.b64 {%0, %1}, %2;" : "=f"(lo), "=f"(hi) : "l"(v));
}
__device__ __forceinline__ float lrelu(float x) { return fmaxf(x, 0.1f * x); }

// ---------------------------------------------------------------------------
// K1: merged Gram kernel.  Blocks 0-127: image Grams.  128-255: caption Grams.
// ---------------------------------------------------------------------------
__global__ __launch_bounds__(256) void k_gram(const float* __restrict__ imgs,
                                              const float* __restrict__ caps) {
    __shared__ float s[N_REG * 132];
    const int b = blockIdx.x, tid = threadIdx.x;
    if (b < N_IMG) {
        const int i = b;
        float acc[6];
#pragma unroll
        for (int j = 0; j < 6; j++) acc[j] = 0.f;
        const float* base = imgs + (size_t)i * N_REG * DIM;
        for (int k0 = 0; k0 < DIM; k0 += 128) {
            for (int idx = tid; idx < N_REG * 128; idx += 256) {
                int r = idx >> 7, k = idx & 127;
                s[r * 132 + k] = base[r * DIM + k0 + k];
            }
            __syncthreads();
#pragma unroll
            for (int j = 0; j < 6; j++) {
                int e = tid + 256 * j;
                if (e < N_REG * N_REG) {
                    int r1 = e / N_REG, r2 = e - r1 * N_REG;
                    const float4* pa = (const float4*)(s + r1 * 132);
                    const float4* pb = (const float4*)(s + r2 * 132);
                    float t = 0.f;
#pragma unroll
                    for (int q = 0; q < 32; q++) {
                        float4 a = pa[q], bb = pb[q];
                        t += a.x * bb.x + a.y * bb.y + a.z * bb.z + a.w * bb.w;
                    }
                    acc[j] += t;
                }
            }
            __syncthreads();
        }
#pragma unroll
        for (int j = 0; j < 6; j++) {
            int e = tid + 256 * j;
            if (e < N_REG * N_REG) g_G[i * N_REG * N_REG + e] = acc[j];
        }
    } else {
        const int c = b - N_IMG;
        float acc[4] = {0.f, 0.f, 0.f, 0.f};
        const float* base = caps + (size_t)c * N_WORD * DIM;
        for (int k0 = 0; k0 < DIM; k0 += 128) {
            for (int idx = tid; idx < N_WORD * 128; idx += 256) {
                int r = idx >> 7, k = idx & 127;
                s[r * 132 + k] = base[r * DIM + k0 + k];
            }
            __syncthreads();
#pragma unroll
            for (int j = 0; j < 4; j++) {
                int e = tid + 256 * j;
                int r1 = e >> 5, r2 = e & 31;
                const float4* pa = (const float4*)(s + r1 * 132);
                const float4* pb = (const float4*)(s + r2 * 132);
                float t = 0.f;
#pragma unroll
                for (int q = 0; q < 32; q++) {
                    float4 a = pa[q], bb = pb[q];
                    t += a.x * bb.x + a.y * bb.y + a.z * bb.z + a.w * bb.w;
                }
                acc[j] += t;
            }
            __syncthreads();
        }
#pragma unroll
        for (int j = 0; j < 4; j++) g_H[c * 1024 + tid + 256 * j] = acc[j];
    }
}

// ---------------------------------------------------------------------------
// K3: raw[c,i,r,w] = images[i,r,:] . captions[c,w,:]
// 4608 x 4096 x 1024 fp32 GEMM (A@B^T), FFMA2 inner, 128x128 tile, BK=16,
// 256 threads, 8x8/thread.  DOUBLE-BUFFERED smem: one barrier per K-tile;
// next-tile STS overlaps current-tile compute; prefetch LDG issues before the
// barrier so L2 latency hides under barrier+compute.
// ---------------------------------------------------------------------------
#define BM 128
#define BN 128
#define BK 16

__global__ __launch_bounds__(256) void k_gemm(const float* __restrict__ A,
                                              const float* __restrict__ B) {
    __shared__ float As[2][BK][BM];    // 16 KB
    __shared__ float Bs[2][BK][BN];    // 16 KB
    const int m0 = blockIdx.y * BM;
    const int n0 = blockIdx.x * BN;
    const int tid = threadIdx.x;
    const int tx = tid & 15, ty = tid >> 4;

    const int idx0 = tid * 2, idx1 = tid * 2 + 1;
    const int r0 = idx0 >> 2, kq0 = (idx0 & 3) * 4;
    const int r1 = idx1 >> 2, kq1 = (idx1 & 3) * 4;

    const float* pa0 = A + (size_t)(m0 + r0) * DIM + kq0;
    const float* pa1 = A + (size_t)(m0 + r1) * DIM + kq1;
    const float* pb0 = B + (size_t)(n0 + r0) * DIM + kq0;
    const float* pb1 = B + (size_t)(n0 + r1) * DIM + kq1;

    u64 acc[8][4];
#pragma unroll
    for (int m = 0; m < 8; m++)
#pragma unroll
        for (int p = 0; p < 4; p++) acc[m][p] = 0ull;

    float4 va0 = *(const float4*)(pa0);
    float4 va1 = *(const float4*)(pa1);
    float4 vb0 = *(const float4*)(pb0);
    float4 vb1 = *(const float4*)(pb1);

#pragma unroll 1
    for (int j = 0; j < DIM / BK; j++) {
        const int buf = j & 1;
        // stage tile j (opposite buffer from tile j-1's in-flight reads)
        As[buf][kq0 + 0][r0] = va0.x; As[buf][kq0 + 1][r0] = va0.y;
        As[buf][kq0 + 2][r0] = va0.z; As[buf][kq0 + 3][r0] = va0.w;
        As[buf][kq1 + 0][r1] = va1.x; As[buf][kq1 + 1][r1] = va1.y;
        As[buf][kq1 + 2][r1] = va1.z; As[buf][kq1 + 3][r1] = va1.w;
        Bs[buf][kq0 + 0][r0] = vb0.x; Bs[buf][kq0 + 1][r0] = vb0.y;
        Bs[buf][kq0 + 2][r0] = vb0.z; Bs[buf][kq0 + 3][r0] = vb0.w;
        Bs[buf][kq1 + 0][r1] = vb1.x; Bs[buf][kq1 + 1][r1] = vb1.y;
        Bs[buf][kq1 + 2][r1] = vb1.z; Bs[buf][kq1 + 3][r1] = vb1.w;

        // prefetch tile j+1 (completes under barrier + compute)
        if (j + 1 < DIM / BK) {
            const int koff = (j + 1) * BK;
            va0 = *(const float4*)(pa0 + koff);
            va1 = *(const float4*)(pa1 + koff);
            vb0 = *(const float4*)(pb0 + koff);
            vb1 = *(const float4*)(pb1 + koff);
        }
        __syncthreads();   // tile j fully staged; all j-1 compute complete

#pragma unroll
        for (int kk = 0; kk < BK; kk++) {
            const float4* ap = (const float4*)(&As[buf][kk][ty * 8]);
            float4 a03 = ap[0], a47 = ap[1];
            u64 a2[8];
            a2[0] = pack_dup(a03.x); a2[1] = pack_dup(a03.y);
            a2[2] = pack_dup(a03.z); a2[3] = pack_dup(a03.w);
            a2[4] = pack_dup(a47.x); a2[5] = pack_dup(a47.y);
            a2[6] = pack_dup(a47.z); a2[7] = pack_dup(a47.w);
            const ulonglong2* bp = (const ulonglong2*)(&Bs[buf][kk][tx * 8]);
            ulonglong2 b01 = bp[0], b23 = bp[1];
            u64 b2[4] = {b01.x, b01.y, b23.x, b23.y};
#pragma unroll
            for (int m = 0; m < 8; m++)
#pragma unroll
                for (int p = 0; p < 4; p++)
                    acc[m][p] = ffma2(a2[m], b2[p], acc[m][p]);
        }
        // no tail barrier: next iteration writes the other buffer
    }

#pragma unroll
    for (int m = 0; m < 8; m++) {
        int gm = m0 + ty * 8 + m;
        int gi = gm / 36, gr = gm - gi * 36;
#pragma unroll
        for (int p = 0; p < 4; p++) {
            float lo, hi;
            unpack2(acc[m][p], lo, hi);
            int gn = n0 + tx * 8 + p * 2;
            int c = gn >> 5, w = gn & 31;
            int base = ((c * N_IMG + gi) * N_REG + gr) * N_WORD + w;
            g_raw[base] = lo;
            g_raw[base + 1] = hi;
        }
    }
}

// ---------------------------------------------------------------------------
// K4: per-(i,c) focal attention + cosine.  64 threads:
// warp0 -> 32 t2i word queries; warp1 -> 36 i2t region queries.
// Reciprocal norms precomputed; no max pass (args bounded); split accums.
// ---------------------------------------------------------------------------
__device__ __forceinline__ float i2t_cos(const float* sraw, const float* sH,
                                         const float* icn, const float* sG, int r) {
    const float* rw = sraw + r * 33;
    float a[N_WORD];
    float s0 = 0.f, s1 = 0.f;
#pragma unroll
    for (int w = 0; w < N_WORD; w++) {
        float e = __expf(20.f * lrelu(rw[w]) * icn[w]);
        a[w] = e;
        if (w & 1) s1 += e; else s0 += e;
    }
    float inv = 1.f / (s0 + s1);
    float u0 = 0.f, u1 = 0.f;
#pragma unroll
    for (int w = 0; w < N_WORD; w++) {
        a[w] *= inv;
        if (w & 1) u1 += a[w]; else u0 += a[w];
    }
    float suma = u0 + u1;
    float t0 = 0.f, t1 = 0.f;
#pragma unroll
    for (int w = 0; w < N_WORD; w++) {
        float t = (a[w] * (float)N_WORD - suma > 0.f) ? a[w] : 0.f;
        a[w] = t;
        if (w & 1) t1 += t; else t0 += t;
    }
    float ist = 1.f / (t0 + t1);
    float n0 = 0.f, n1 = 0.f;
#pragma unroll
    for (int w = 0; w < N_WORD; w++) {
        a[w] *= ist;
        if (w & 1) n1 += a[w] * rw[w]; else n0 += a[w] * rw[w];
    }
    float num = n0 + n1;
    float d2a = 0.f, d2b = 0.f;
#pragma unroll
    for (int w = 0; w < N_WORD; w++) {
        const float4* h4 = (const float4*)(sH + w * N_WORD);
        float q0 = 0.f, q1 = 0.f;
#pragma unroll
        for (int jj = 0; jj < 8; jj++) {
            float4 v = h4[jj];
            float p = v.x * a[4 * jj] + v.y * a[4 * jj + 1] + v.z * a[4 * jj + 2] + v.w * a[4 * jj + 3];
            if (jj & 1) q1 += p; else q0 += p;
        }
        if (w & 1) d2b += a[w] * (q0 + q1); else d2a += a[w] * (q0 + q1);
    }
    float imgn = fmaxf(sqrtf(sG[r * N_REG + r]), 1e-8f);
    float wn = fmaxf(sqrtf(fmaxf(d2a + d2b, 0.f)), 1e-8f);
    return num / (imgn * wn);
}

__global__ __launch_bounds__(64) void k_attn(float* __restrict__ out) {
    const int i = blockIdx.x, c = blockIdx.y;
    const int tid = threadIdx.x, lane = tid & 31;

    __shared__ float sraw[N_REG * 33];
    __shared__ float sG[N_REG * N_REG];
    __shared__ float sH[N_WORD * N_WORD];
    __shared__ float irn[N_REG], icn[N_WORD];
    __shared__ float redT, redI;

    const float* praw = g_raw + (size_t)(c * N_IMG + i) * (N_REG * N_WORD);
    for (int idx = tid; idx < N_REG * N_WORD; idx += 64)
        sraw[(idx >> 5) * 33 + (idx & 31)] = praw[idx];
    const float* pG = g_G + i * (N_REG * N_REG);
    for (int idx = tid; idx < N_REG * N_REG; idx += 64) sG[idx] = pG[idx];
    const float* pH = g_H + c * (N_WORD * N_WORD);
    for (int idx = tid; idx < N_WORD * N_WORD; idx += 64) sH[idx] = pH[idx];
    __syncthreads();

    if (tid < 32) {
        float s0 = 0.f, s1 = 0.f;
#pragma unroll
        for (int w = 0; w < N_WORD; w++) {
            float x = lrelu(sraw[tid * 33 + w]);
            if (w & 1) s1 += x * x; else s0 += x * x;
        }
        irn[tid] = 1.f / (sqrtf(s0 + s1) + 1e-8f);
    } else {
        int col = tid - 32;
        float s0 = 0.f, s1 = 0.f;
#pragma unroll
        for (int r = 0; r < N_REG; r++) {
            float x = lrelu(sraw[r * 33 + col]);
            if (r & 1) s1 += x * x; else s0 += x * x;
        }
        icn[col] = 1.f / (sqrtf(s0 + s1) + 1e-8f);
        if (col < 4) {
            int rr = 32 + col;
            float t0 = 0.f, t1 = 0.f;
#pragma unroll
            for (int w = 0; w < N_WORD; w++) {
                float x = lrelu(sraw[rr * 33 + w]);
                if (w & 1) t1 += x * x; else t0 += x * x;
            }
            irn[rr] = 1.f / (sqrtf(t0 + t1) + 1e-8f);
        }
    }
    __syncthreads();

    if (tid < 32) {
        const int w = tid;
        float a[N_REG];
        float s0 = 0.f, s1 = 0.f;
#pragma unroll
        for (int r = 0; r < N_REG; r++) {
            float e = __expf(20.f * lrelu(sraw[r * 33 + w]) * irn[r]);
            a[r] = e;
            if (r & 1) s1 += e; else s0 += e;
        }
        float inv = 1.f / (s0 + s1);
        float u0 = 0.f, u1 = 0.f;
#pragma unroll
        for (int r = 0; r < N_REG; r++) {
            a[r] *= inv;
            if (r & 1) u1 += a[r]; else u0 += a[r];
        }
        float suma = u0 + u1;
        float t0 = 0.f, t1 = 0.f;
#pragma unroll
        for (int r = 0; r < N_REG; r++) {
            float t = (a[r] * (float)N_REG - suma > 0.f) ? a[r] : 0.f;
            a[r] = t;
            if (r & 1) t1 += t; else t0 += t;
        }
        float ist = 1.f / (t0 + t1);
        float m0 = 0.f, m1 = 0.f;
#pragma unroll
        for (int r = 0; r < N_REG; r++) {
            a[r] *= ist;
            if (r & 1) m1 += a[r] * sraw[r * 33 + w]; else m0 += a[r] * sraw[r * 33 + w];
        }
        float num = m0 + m1;
        float d2a = 0.f, d2b = 0.f;
#pragma unroll
        for (int r = 0; r < N_REG; r++) {
            const float4* g4 = (const float4*)(sG + r * N_REG);
            float q0 = 0.f, q1 = 0.f;
#pragma unroll
            for (int jj = 0; jj < 9; jj++) {
                float4 v = g4[jj];
                float p = v.x * a[4 * jj] + v.y * a[4 * jj + 1] + v.z * a[4 * jj + 2] + v.w * a[4 * jj + 3];
                if (jj & 1) q1 += p; else q0 += p;
            }
            if (r & 1) d2b += a[r] * (q0 + q1); else d2a += a[r] * (q0 + q1);
        }
        float capn = fmaxf(sqrtf(sH[w * N_WORD + w]), 1e-8f);
        float wn = fmaxf(sqrtf(fmaxf(d2a + d2b, 0.f)), 1e-8f);
        float v = num / (capn * wn);
#pragma unroll
        for (int off = 16; off; off >>= 1) v += __shfl_xor_sync(0xffffffffu, v, off);
        if (lane == 0) redT = v;
    } else {
        float v = i2t_cos(sraw, sH, icn, sG, lane);
        if (lane >= 28) v += i2t_cos(sraw, sH, icn, sG, lane + 4);
#pragma unroll
        for (int off = 16; off; off >>= 1) v += __shfl_xor_sync(0xffffffffu, v, off);
        if (lane == 0) redI = v;
    }
    __syncthreads();
    if (tid == 0)
        out[i * N_CAP + c] = redT * (1.f / N_WORD) + redI * (1.f / N_REG);
}

// ---------------------------------------------------------------------------
extern "C" void kernel_launch(void* const* d_in, const int* in_sizes, int n_in,
                              void* d_out, int out_size) {
    const float* images = (const float*)d_in[0];     // (128, 36, 1024)
    const float* captions = (const float*)d_in[1];   // (128, 32, 1024)
    float* out = (float*)d_out;                      // (128, 128)

    k_gram<<<N_IMG + N_CAP, 256>>>(images, captions);
    k_gemm<<<dim3((N_CAP * N_WORD) / BN, (N_IMG * N_REG) / BM), 256>>>(images, captions);
    k_attn<<<dim3(N_IMG, N_CAP), 64>>>(out);
}